// round 9
// baseline (speedup 1.0000x reference)
#include <cuda_runtime.h>
#include <cuda_fp16.h>
#include <cstdint>

#define N_NODES 100000
#define N_EDGES 1250000
#define D 64
#define SCAN_B2 ((N_NODES + 1023) / 1024)   // 98

// Scratch (static device globals — no allocation allowed)
__device__ __align__(128) __half g_xh[(size_t)N_NODES * D];   // fp16 x
__device__ __align__(128) __half g_a1h[(size_t)N_NODES * D];  // fp16 A1=agg(x)
__device__ __align__(128) float  g_a2[(size_t)N_NODES * D];   // fp32 A2=agg(A1)
__device__ float g_W2[D * D];                  // W @ W
__device__ float g_bW[D];                      // b @ W^T
__device__ int   g_deg[N_NODES];
__device__ int   g_off[N_NODES + 4];
__device__ int   g_cur[N_NODES];
__device__ int   g_srcs[N_EDGES];
__device__ int   g_bsum[SCAN_B2];
__device__ int   g_boff[SCAN_B2];
__device__ int   g_is64;

// ---------------------------------------------------------------------------
// init: detect int64 vs int32 edge layout + zero degree counters
// ---------------------------------------------------------------------------
__global__ void init_kernel(const unsigned* __restrict__ ei) {
    int i = blockIdx.x * blockDim.x + threadIdx.x;
    if (i < N_NODES) g_deg[i] = 0;
    if (i == 0) {
        int all0 = 1;
        #pragma unroll 1
        for (int k = 0; k < 64; k++) {
            if (ei[2 * k + 1] != 0u) { all0 = 0; break; }
        }
        g_is64 = all0;
    }
}

// ---------------------------------------------------------------------------
// prep (17 blocks): W2 = W @ W,  bW = b @ W^T
// ---------------------------------------------------------------------------
__global__ void prep_kernel(const float* __restrict__ W,
                            const float* __restrict__ b) {
    __shared__ float Wsh[D * D];
    int t = threadIdx.x;                 // 256
    #pragma unroll
    for (int i = t; i < D * D; i += 256) Wsh[i] = W[i];
    __syncthreads();
    if (blockIdx.x < 16) {
        int o = blockIdx.x * 256 + t;
        int j = o >> 6, k = o & 63;
        float s = 0.f;
        #pragma unroll
        for (int m = 0; m < D; m++) s += Wsh[j * D + m] * Wsh[m * D + k];
        g_W2[o] = s;
    } else if (t < D) {
        float s = 0.f;
        #pragma unroll
        for (int k = 0; k < D; k++) s += b[k] * Wsh[t * D + k];
        g_bW[t] = s;
    }
}

// ---------------------------------------------------------------------------
// convert x (fp32) -> g_xh (fp16). One thread per 8 elements.
// ---------------------------------------------------------------------------
__global__ void convert_kernel(const float* __restrict__ x) {
    int i = blockIdx.x * blockDim.x + threadIdx.x;   // over N*D/8
    const int n = N_NODES * D / 8;
    if (i >= n) return;
    float4 a = reinterpret_cast<const float4*>(x)[2 * i];
    float4 c = reinterpret_cast<const float4*>(x)[2 * i + 1];
    __half2 h0 = __floats2half2_rn(a.x, a.y);
    __half2 h1 = __floats2half2_rn(a.z, a.w);
    __half2 h2 = __floats2half2_rn(c.x, c.y);
    __half2 h3 = __floats2half2_rn(c.z, c.w);
    uint4 o;
    o.x = *reinterpret_cast<unsigned*>(&h0);
    o.y = *reinterpret_cast<unsigned*>(&h1);
    o.z = *reinterpret_cast<unsigned*>(&h2);
    o.w = *reinterpret_cast<unsigned*>(&h3);
    reinterpret_cast<uint4*>(g_xh)[i] = o;
}

// ---------------------------------------------------------------------------
// CSR build: histogram (4/thread) -> scan (1024/block) -> fill (4/thread)
// ---------------------------------------------------------------------------
__global__ void hist_kernel(const void* __restrict__ ei) {
    int q = blockIdx.x * blockDim.x + threadIdx.x;
    int e = q * 4;
    if (e >= N_EDGES) return;
    int d0, d1, d2, d3;
    if (g_is64) {
        const longlong2* p = reinterpret_cast<const longlong2*>(
            (const long long*)ei + N_EDGES + e);
        longlong2 a = __ldg(p), c = __ldg(p + 1);
        d0 = (int)a.x; d1 = (int)a.y; d2 = (int)c.x; d3 = (int)c.y;
    } else {
        int4 a = __ldg(reinterpret_cast<const int4*>((const int*)ei + N_EDGES + e));
        d0 = a.x; d1 = a.y; d2 = a.z; d3 = a.w;
    }
    atomicAdd(&g_deg[d0], 1);
    atomicAdd(&g_deg[d1], 1);
    atomicAdd(&g_deg[d2], 1);
    atomicAdd(&g_deg[d3], 1);
}

// Phase 1: per-block sums, 1024 elements per block (int4 per thread).
__global__ void partial_kernel() {
    __shared__ int ws[8];
    int t = threadIdx.x;
    int i4 = blockIdx.x * 1024 + t * 4;
    int v = 0;
    if (i4 < N_NODES) {                  // N_NODES % 4 == 0 -> full int4
        int4 a = *reinterpret_cast<const int4*>(&g_deg[i4]);
        v = a.x + a.y + a.z + a.w;
    }
    #pragma unroll
    for (int o = 16; o > 0; o >>= 1) v += __shfl_down_sync(0xffffffffu, v, o);
    if ((t & 31) == 0) ws[t >> 5] = v;
    __syncthreads();
    if (t == 0) {
        int s = 0;
        #pragma unroll
        for (int i = 0; i < 8; i++) s += ws[i];
        g_bsum[blockIdx.x] = s;
    }
}

// Phase 2: exclusive scan of the 98 block sums (single block, 128 threads).
__global__ void scan_bsums_kernel() {
    __shared__ int ws[4];
    int t = threadIdx.x;           // 128 threads
    int lane = t & 31, wid = t >> 5;
    int v = (t < SCAN_B2) ? g_bsum[t] : 0;
    int incl = v;
    #pragma unroll
    for (int o = 1; o < 32; o <<= 1) {
        int n = __shfl_up_sync(0xffffffffu, incl, o);
        if (lane >= o) incl += n;
    }
    if (lane == 31) ws[wid] = incl;
    __syncthreads();
    if (wid == 0 && lane < 4) {
        int w = ws[lane];
        #pragma unroll
        for (int o = 1; o < 4; o <<= 1) {
            int n = __shfl_up_sync(0x0000000fu, w, o);
            if (lane >= o) w += n;
        }
        ws[lane] = w;
    }
    __syncthreads();
    int excl = incl - v + (wid ? ws[wid - 1] : 0);
    if (t < SCAN_B2) g_boff[t] = excl;
    if (t == 0) g_off[N_NODES] = N_EDGES;
}

// Phase 3: per-block exclusive scan (1024/block, int4) + offsets.
__global__ void write_off_kernel() {
    __shared__ int ws[8];
    int t = threadIdx.x;
    int lane = t & 31, wid = t >> 5;
    int i4 = blockIdx.x * 1024 + t * 4;
    int4 a = make_int4(0, 0, 0, 0);
    if (i4 < N_NODES) a = *reinterpret_cast<const int4*>(&g_deg[i4]);
    int s4 = a.x + a.y + a.z + a.w;
    int incl = s4;
    #pragma unroll
    for (int o = 1; o < 32; o <<= 1) {
        int n = __shfl_up_sync(0xffffffffu, incl, o);
        if (lane >= o) incl += n;
    }
    if (lane == 31) ws[wid] = incl;
    __syncthreads();
    if (wid == 0 && lane < 8) {
        int w = ws[lane];
        #pragma unroll
        for (int o = 1; o < 8; o <<= 1) {
            int n = __shfl_up_sync(0x000000ffu, w, o);
            if (lane >= o) w += n;
        }
        ws[lane] = w;
    }
    __syncthreads();
    int base = incl - s4 + (wid ? ws[wid - 1] : 0) + g_boff[blockIdx.x];
    if (i4 < N_NODES) {
        int4 o;
        o.x = base;
        o.y = base + a.x;
        o.z = base + a.x + a.y;
        o.w = base + a.x + a.y + a.z;
        *reinterpret_cast<int4*>(&g_off[i4]) = o;
        *reinterpret_cast<int4*>(&g_cur[i4]) = o;
    }
}

__global__ void fill_kernel(const void* __restrict__ ei) {
    int q = blockIdx.x * blockDim.x + threadIdx.x;
    int e = q * 4;
    if (e >= N_EDGES) return;
    int s0, s1, s2, s3, d0, d1, d2, d3;
    if (g_is64) {
        const longlong2* ps = reinterpret_cast<const longlong2*>((const long long*)ei + e);
        const longlong2* pd = reinterpret_cast<const longlong2*>((const long long*)ei + N_EDGES + e);
        longlong2 a = __ldg(ps), c = __ldg(ps + 1);
        longlong2 u = __ldg(pd), w = __ldg(pd + 1);
        s0 = (int)a.x; s1 = (int)a.y; s2 = (int)c.x; s3 = (int)c.y;
        d0 = (int)u.x; d1 = (int)u.y; d2 = (int)w.x; d3 = (int)w.y;
    } else {
        int4 a = __ldg(reinterpret_cast<const int4*>((const int*)ei + e));
        int4 u = __ldg(reinterpret_cast<const int4*>((const int*)ei + N_EDGES + e));
        s0 = a.x; s1 = a.y; s2 = a.z; s3 = a.w;
        d0 = u.x; d1 = u.y; d2 = u.z; d3 = u.w;
    }
    g_srcs[atomicAdd(&g_cur[d0], 1)] = s0;
    g_srcs[atomicAdd(&g_cur[d1], 1)] = s1;
    g_srcs[atomicAdd(&g_cur[d2], 1)] = s2;
    g_srcs[atomicAdd(&g_cur[d3], 1)] = s3;
}

// ---------------------------------------------------------------------------
// Gather (fp16 reads, fp32 accumulate): 16 lanes/node, 4 halfs (uint2) each.
//   phase 0: g_xh  -> g_a1h (fp16 out)
//   phase 1: g_a1h -> g_a2  (fp32 out)
// 8-edge batches for MLP=8 on both the index and row load levels.
// ---------------------------------------------------------------------------
__global__ void gather_h_kernel(int phase) {
    int t = blockIdx.x * blockDim.x + threadIdx.x;
    int node = t >> 4;
    int c = t & 15;
    if (node >= N_NODES) return;

    const __half* in = phase ? g_a1h : g_xh;

    int beg = __ldg(&g_off[node]);
    int end = __ldg(&g_off[node + 1]);

    float a0 = 0.f, a1 = 0.f, a2 = 0.f, a3 = 0.f;
    int e = beg;
    for (; e + 8 <= end; e += 8) {
        int s[8];
        #pragma unroll
        for (int i = 0; i < 8; i++) s[i] = __ldg(&g_srcs[e + i]);
        uint2 v[8];
        #pragma unroll
        for (int i = 0; i < 8; i++)
            v[i] = *reinterpret_cast<const uint2*>(in + (size_t)s[i] * D + c * 4);
        #pragma unroll
        for (int i = 0; i < 8; i++) {
            float2 f0 = __half22float2(*reinterpret_cast<__half2*>(&v[i].x));
            float2 f1 = __half22float2(*reinterpret_cast<__half2*>(&v[i].y));
            a0 += f0.x; a1 += f0.y; a2 += f1.x; a3 += f1.y;
        }
    }
    #pragma unroll 4
    for (; e < end; e++) {
        int s = __ldg(&g_srcs[e]);
        uint2 v = *reinterpret_cast<const uint2*>(in + (size_t)s * D + c * 4);
        float2 f0 = __half22float2(*reinterpret_cast<__half2*>(&v.x));
        float2 f1 = __half22float2(*reinterpret_cast<__half2*>(&v.y));
        a0 += f0.x; a1 += f0.y; a2 += f1.x; a3 += f1.y;
    }

    if (phase == 0) {
        __half2 h0 = __floats2half2_rn(a0, a1);
        __half2 h1 = __floats2half2_rn(a2, a3);
        uint2 o;
        o.x = *reinterpret_cast<unsigned*>(&h0);
        o.y = *reinterpret_cast<unsigned*>(&h1);
        *reinterpret_cast<uint2*>(g_a1h + (size_t)node * D + c * 4) = o;
    } else {
        *reinterpret_cast<float4*>(g_a2 + (size_t)node * D + c * 4) =
            make_float4(a0, a1, a2, a3);
    }
}

// ---------------------------------------------------------------------------
// Dual GEMM per 64-row tile:
//   phase 1:  hid = A1 @ W^T  + b          (A1 fp16 -> fp32 smem)
//   phase 2:  out = A2 @ W2^T + deg*bW + b (A2 fp32)
// 4x4 register tile, fma.rn.f32x2 (FFMA2).
// ---------------------------------------------------------------------------
#define SROW 68

__device__ __forceinline__ void stage_a_tile_h(float* As, int row0, int t) {
    #pragma unroll
    for (int i = t; i < 64 * 8; i += 256) {      // 8 uint4 per row
        int r = i >> 3, c8 = i & 7;
        int row = row0 + r;
        float4 lo = make_float4(0.f, 0.f, 0.f, 0.f), hi = lo;
        if (row < N_NODES) {
            uint4 v = *reinterpret_cast<const uint4*>(g_a1h + (size_t)row * D + c8 * 8);
            float2 f0 = __half22float2(*reinterpret_cast<__half2*>(&v.x));
            float2 f1 = __half22float2(*reinterpret_cast<__half2*>(&v.y));
            float2 f2 = __half22float2(*reinterpret_cast<__half2*>(&v.z));
            float2 f3 = __half22float2(*reinterpret_cast<__half2*>(&v.w));
            lo = make_float4(f0.x, f0.y, f1.x, f1.y);
            hi = make_float4(f2.x, f2.y, f3.x, f3.y);
        }
        *reinterpret_cast<float4*>(&As[r * SROW + c8 * 8])     = lo;
        *reinterpret_cast<float4*>(&As[r * SROW + c8 * 8 + 4]) = hi;
    }
}

__device__ __forceinline__ void stage_a_tile_f(float* As, int row0, int t) {
    #pragma unroll
    for (int i = t; i < 64 * 16; i += 256) {
        int r = i >> 4, k4 = i & 15;
        int row = row0 + r;
        float4 v = make_float4(0.f, 0.f, 0.f, 0.f);
        if (row < N_NODES)
            v = reinterpret_cast<const float4*>(g_a2)[(size_t)row * 16 + k4];
        *reinterpret_cast<float4*>(&As[r * SROW + k4 * 4]) = v;
    }
}

__device__ __forceinline__ void gemm_tile(const float* As, const float* Ws,
                                          unsigned long long acc[4][4],
                                          int tx, int ty) {
    #pragma unroll 4
    for (int k4 = 0; k4 < 16; k4++) {
        ulonglong2 a[4], w[4];
        #pragma unroll
        for (int ri = 0; ri < 4; ri++)
            a[ri] = *reinterpret_cast<const ulonglong2*>(&As[(ty * 4 + ri) * SROW + k4 * 4]);
        #pragma unroll
        for (int ji = 0; ji < 4; ji++)
            w[ji] = *reinterpret_cast<const ulonglong2*>(&Ws[(tx + 16 * ji) * SROW + k4 * 4]);
        #pragma unroll
        for (int ri = 0; ri < 4; ri++)
            #pragma unroll
            for (int ji = 0; ji < 4; ji++) {
                asm("fma.rn.f32x2 %0, %1, %2, %0;"
                    : "+l"(acc[ri][ji]) : "l"(a[ri].x), "l"(w[ji].x));
                asm("fma.rn.f32x2 %0, %1, %2, %0;"
                    : "+l"(acc[ri][ji]) : "l"(a[ri].y), "l"(w[ji].y));
            }
    }
}

__global__ __launch_bounds__(256) void dual_linear_kernel(
        float* __restrict__ hid, float* __restrict__ out,
        const float* __restrict__ W, const float* __restrict__ b) {
    __shared__ __align__(16) float As[64 * SROW];
    __shared__ __align__(16) float Ws[64 * SROW];

    const int t = threadIdx.x;           // 256 threads
    const int row0 = blockIdx.x * 64;
    const int tx = t & 15;
    const int ty = t >> 4;

    // ---- phase 1: hid = A1 @ W^T + b ----
    #pragma unroll
    for (int i = t; i < 64 * 16; i += 256) {
        int j = i >> 4, k4 = i & 15;
        *reinterpret_cast<float4*>(&Ws[j * SROW + k4 * 4]) =
            reinterpret_cast<const float4*>(W)[j * 16 + k4];
    }
    stage_a_tile_h(As, row0, t);
    __syncthreads();

    {
        unsigned long long acc[4][4];
        #pragma unroll
        for (int ri = 0; ri < 4; ri++)
            #pragma unroll
            for (int ji = 0; ji < 4; ji++) acc[ri][ji] = 0ull;
        gemm_tile(As, Ws, acc, tx, ty);
        float bj[4];
        #pragma unroll
        for (int ji = 0; ji < 4; ji++) bj[ji] = __ldg(&b[tx + 16 * ji]);
        #pragma unroll
        for (int ri = 0; ri < 4; ri++) {
            int row = row0 + ty * 4 + ri;
            if (row < N_NODES) {
                #pragma unroll
                for (int ji = 0; ji < 4; ji++) {
                    float lo, hi;
                    asm("mov.b64 {%0, %1}, %2;" : "=f"(lo), "=f"(hi) : "l"(acc[ri][ji]));
                    hid[(size_t)row * D + tx + 16 * ji] = lo + hi + bj[ji];
                }
            }
        }
    }
    __syncthreads();

    // ---- phase 2: out = A2 @ W2^T + deg*bW + b ----
    #pragma unroll
    for (int i = t; i < 64 * 16; i += 256) {
        int j = i >> 4, k4 = i & 15;
        *reinterpret_cast<float4*>(&Ws[j * SROW + k4 * 4]) =
            reinterpret_cast<const float4*>(g_W2)[j * 16 + k4];
    }
    stage_a_tile_f(As, row0, t);
    __syncthreads();

    {
        unsigned long long acc[4][4];
        #pragma unroll
        for (int ri = 0; ri < 4; ri++)
            #pragma unroll
            for (int ji = 0; ji < 4; ji++) acc[ri][ji] = 0ull;
        gemm_tile(As, Ws, acc, tx, ty);
        float bj[4], bWj[4];
        #pragma unroll
        for (int ji = 0; ji < 4; ji++) {
            bj[ji]  = __ldg(&b[tx + 16 * ji]);
            bWj[ji] = __ldg(&g_bW[tx + 16 * ji]);
        }
        #pragma unroll
        for (int ri = 0; ri < 4; ri++) {
            int row = row0 + ty * 4 + ri;
            if (row < N_NODES) {
                float degf = __int2float_rn(__ldg(&g_deg[row]));
                #pragma unroll
                for (int ji = 0; ji < 4; ji++) {
                    float lo, hi;
                    asm("mov.b64 {%0, %1}, %2;" : "=f"(lo), "=f"(hi) : "l"(acc[ri][ji]));
                    out[(size_t)row * D + tx + 16 * ji] = lo + hi + degf * bWj[ji] + bj[ji];
                }
            }
        }
    }
}

// ---------------------------------------------------------------------------
extern "C" void kernel_launch(void* const* d_in, const int* in_sizes, int n_in,
                              void* d_out, int out_size) {
    const float* x  = (const float*)d_in[0];
    const void*  ei = d_in[1];
    const float* W1 = (const float*)d_in[2];
    const float* b1 = (const float*)d_in[3];

    float* out = (float*)d_out;                      // (out, hid) flattened
    float* hid = out + (size_t)N_NODES * D;

    const int E4BLK = (N_EDGES / 4 + 255) / 256;     // 1221
    const int NBLK  = (N_NODES + 255) / 256;
    const int CBLK  = (N_NODES * D / 8 + 255) / 256;
    const int GBLK  = (N_NODES * 16 + 255) / 256;    // 6250
    const int FBLK  = (N_NODES + 63) / 64;           // 1563

    init_kernel<<<NBLK, 256>>>((const unsigned*)ei);
    prep_kernel<<<17, 256>>>(W1, b1);
    convert_kernel<<<CBLK, 256>>>(x);

    hist_kernel<<<E4BLK, 256>>>(ei);
    partial_kernel<<<SCAN_B2, 256>>>();
    scan_bsums_kernel<<<1, 128>>>();
    write_off_kernel<<<SCAN_B2, 256>>>();
    fill_kernel<<<E4BLK, 256>>>(ei);

    gather_h_kernel<<<GBLK, 256>>>(0);               // A1 = agg(x)   (fp16)
    gather_h_kernel<<<GBLK, 256>>>(1);               // A2 = agg(A1)  (fp32)
    dual_linear_kernel<<<FBLK, 256>>>(hid, out, W1, b1);
}

// round 10
// speedup vs baseline: 1.0049x; 1.0049x over previous
#include <cuda_runtime.h>
#include <cstdint>

#define N_NODES 100000
#define N_EDGES 1250000
#define D 64
#define ZBLKS ((N_NODES + 1023) / 1024)   // 98

// Scratch (static device globals — no allocation allowed)
__device__ __align__(128) float g_a1[(size_t)N_NODES * D];  // A1 = agg(x)
__device__ __align__(128) float g_a2[(size_t)N_NODES * D];  // A2 = agg(A1)
__device__ float g_W2[D * D];                  // W @ W
__device__ float g_bW[D];                      // b @ W^T
__device__ int   g_deg[N_NODES];
__device__ int   g_off[N_NODES + 4];
__device__ int   g_cur[N_NODES];
__device__ int   g_srcs[N_EDGES];
__device__ int   g_is64;

// ---------------------------------------------------------------------------
// Fused init: blocks [0,98) zero g_deg; [98,114) compute W2; 114: bW + detect.
// ---------------------------------------------------------------------------
__global__ void init2_kernel(const unsigned* __restrict__ ei,
                             const float* __restrict__ W,
                             const float* __restrict__ b) {
    int t = threadIdx.x;                 // 256
    int bid = blockIdx.x;
    if (bid < ZBLKS) {
        int i4 = bid * 1024 + t * 4;
        if (i4 < N_NODES)
            *reinterpret_cast<int4*>(&g_deg[i4]) = make_int4(0, 0, 0, 0);
        return;
    }
    __shared__ float Wsh[D * D];
    #pragma unroll
    for (int i = t; i < D * D; i += 256) Wsh[i] = W[i];
    __syncthreads();
    if (bid < ZBLKS + 16) {
        int o = (bid - ZBLKS) * 256 + t;
        int j = o >> 6, k = o & 63;
        float s = 0.f;
        #pragma unroll
        for (int m = 0; m < D; m++) s += Wsh[j * D + m] * Wsh[m * D + k];
        g_W2[o] = s;
    } else {
        if (t < D) {
            float s = 0.f;
            #pragma unroll
            for (int k = 0; k < D; k++) s += b[k] * Wsh[t * D + k];
            g_bW[t] = s;
        } else if (t == 64) {
            int all0 = 1;
            #pragma unroll 1
            for (int k = 0; k < 64; k++) {
                if (ei[2 * k + 1] != 0u) { all0 = 0; break; }
            }
            g_is64 = all0;
        }
    }
}

// ---------------------------------------------------------------------------
// Histogram over dst (4 edges/thread, vectorized loads).
// ---------------------------------------------------------------------------
__global__ void hist_kernel(const void* __restrict__ ei) {
    int q = blockIdx.x * blockDim.x + threadIdx.x;
    int e = q * 4;
    if (e >= N_EDGES) return;
    int d0, d1, d2, d3;
    if (g_is64) {
        const longlong2* p = reinterpret_cast<const longlong2*>(
            (const long long*)ei + N_EDGES + e);
        longlong2 a = __ldg(p), c = __ldg(p + 1);
        d0 = (int)a.x; d1 = (int)a.y; d2 = (int)c.x; d3 = (int)c.y;
    } else {
        int4 a = __ldg(reinterpret_cast<const int4*>((const int*)ei + N_EDGES + e));
        d0 = a.x; d1 = a.y; d2 = a.z; d3 = a.w;
    }
    atomicAdd(&g_deg[d0], 1);
    atomicAdd(&g_deg[d1], 1);
    atomicAdd(&g_deg[d2], 1);
    atomicAdd(&g_deg[d3], 1);
}

// ---------------------------------------------------------------------------
// One-launch exclusive scan: each of 98 blocks redundantly sums all preceding
// degrees (O(n^2/2) int reads = ~19.5 MB of L2, cheap) then scans its own
// 1024-element slice and writes g_off / g_cur. No inter-block dependencies.
// ---------------------------------------------------------------------------
__global__ void scanoff_kernel() {
    __shared__ int ws[8];
    __shared__ int base_sh;
    int t = threadIdx.x;                 // 256
    int lane = t & 31, wid = t >> 5;
    int start = blockIdx.x * 1024;

    // --- sum of g_deg[0, start) ---
    int pre = 0;
    int num4 = start >> 2;
    for (int i = t; i < num4; i += 256) {
        int4 a = *reinterpret_cast<const int4*>(&g_deg[i * 4]);
        pre += a.x + a.y + a.z + a.w;
    }
    #pragma unroll
    for (int o = 16; o > 0; o >>= 1) pre += __shfl_down_sync(0xffffffffu, pre, o);
    if (lane == 0) ws[wid] = pre;
    __syncthreads();
    if (t == 0) {
        int s = 0;
        #pragma unroll
        for (int i = 0; i < 8; i++) s += ws[i];
        base_sh = s;
    }
    __syncthreads();

    // --- exclusive scan of own 1024 slice (4 per thread) ---
    int i4 = start + t * 4;
    int4 a = make_int4(0, 0, 0, 0);
    if (i4 < N_NODES) a = *reinterpret_cast<const int4*>(&g_deg[i4]);
    int s4 = a.x + a.y + a.z + a.w;
    int incl = s4;
    #pragma unroll
    for (int o = 1; o < 32; o <<= 1) {
        int n = __shfl_up_sync(0xffffffffu, incl, o);
        if (lane >= o) incl += n;
    }
    if (lane == 31) ws[wid] = incl;
    __syncthreads();
    if (wid == 0 && lane < 8) {
        int w = ws[lane];
        #pragma unroll
        for (int o = 1; o < 8; o <<= 1) {
            int n = __shfl_up_sync(0x000000ffu, w, o);
            if (lane >= o) w += n;
        }
        ws[lane] = w;
    }
    __syncthreads();
    int base = incl - s4 + (wid ? ws[wid - 1] : 0) + base_sh;
    if (i4 < N_NODES) {
        int4 o;
        o.x = base;
        o.y = base + a.x;
        o.z = base + a.x + a.y;
        o.w = base + a.x + a.y + a.z;
        *reinterpret_cast<int4*>(&g_off[i4]) = o;
        *reinterpret_cast<int4*>(&g_cur[i4]) = o;
    }
    if (blockIdx.x == 0 && t == 0) g_off[N_NODES] = N_EDGES;
}

// ---------------------------------------------------------------------------
// Fill CSR adjacency (4 edges/thread).
// ---------------------------------------------------------------------------
__global__ void fill_kernel(const void* __restrict__ ei) {
    int q = blockIdx.x * blockDim.x + threadIdx.x;
    int e = q * 4;
    if (e >= N_EDGES) return;
    int s0, s1, s2, s3, d0, d1, d2, d3;
    if (g_is64) {
        const longlong2* ps = reinterpret_cast<const longlong2*>((const long long*)ei + e);
        const longlong2* pd = reinterpret_cast<const longlong2*>((const long long*)ei + N_EDGES + e);
        longlong2 a = __ldg(ps), c = __ldg(ps + 1);
        longlong2 u = __ldg(pd), w = __ldg(pd + 1);
        s0 = (int)a.x; s1 = (int)a.y; s2 = (int)c.x; s3 = (int)c.y;
        d0 = (int)u.x; d1 = (int)u.y; d2 = (int)w.x; d3 = (int)w.y;
    } else {
        int4 a = __ldg(reinterpret_cast<const int4*>((const int*)ei + e));
        int4 u = __ldg(reinterpret_cast<const int4*>((const int*)ei + N_EDGES + e));
        s0 = a.x; s1 = a.y; s2 = a.z; s3 = a.w;
        d0 = u.x; d1 = u.y; d2 = u.z; d3 = u.w;
    }
    g_srcs[atomicAdd(&g_cur[d0], 1)] = s0;
    g_srcs[atomicAdd(&g_cur[d1], 1)] = s1;
    g_srcs[atomicAdd(&g_cur[d2], 1)] = s2;
    g_srcs[atomicAdd(&g_cur[d3], 1)] = s3;
}

// ---------------------------------------------------------------------------
// Gather (fp32): phase 0: x -> g_a1, phase 1: g_a1 -> g_a2.
// 16 lanes per node (one float4 each); 8-edge batches for MLP=8.
// ---------------------------------------------------------------------------
__global__ void gather_kernel(const float* __restrict__ x, int phase) {
    int t = blockIdx.x * blockDim.x + threadIdx.x;
    int node = t >> 4;
    int c = t & 15;
    if (node >= N_NODES) return;

    const float* in = phase ? g_a1 : x;
    float* outp     = phase ? g_a2 : g_a1;

    int beg = __ldg(&g_off[node]);
    int end = __ldg(&g_off[node + 1]);

    float4 acc = make_float4(0.f, 0.f, 0.f, 0.f);
    int e = beg;
    for (; e + 8 <= end; e += 8) {
        int s[8];
        #pragma unroll
        for (int i = 0; i < 8; i++) s[i] = __ldg(&g_srcs[e + i]);
        float4 v[8];
        #pragma unroll
        for (int i = 0; i < 8; i++)
            v[i] = *reinterpret_cast<const float4*>(in + (size_t)s[i] * D + c * 4);
        #pragma unroll
        for (int i = 0; i < 8; i++) {
            acc.x += v[i].x; acc.y += v[i].y; acc.z += v[i].z; acc.w += v[i].w;
        }
    }
    #pragma unroll 4
    for (; e < end; e++) {
        int s = __ldg(&g_srcs[e]);
        float4 v = *reinterpret_cast<const float4*>(in + (size_t)s * D + c * 4);
        acc.x += v.x; acc.y += v.y; acc.z += v.z; acc.w += v.w;
    }
    *reinterpret_cast<float4*>(outp + (size_t)node * D + c * 4) = acc;
}

// ---------------------------------------------------------------------------
// Dual GEMM per 64-row tile:
//   phase 1:  hid = A1 @ W^T  + b
//   phase 2:  out = A2 @ W2^T + deg*bW + b
// 4x4 register tile, fma.rn.f32x2 (FFMA2).
// ---------------------------------------------------------------------------
#define SROW 68

__device__ __forceinline__ void stage_a_tile(float* As, const float* __restrict__ src,
                                             int row0, int t) {
    #pragma unroll
    for (int i = t; i < 64 * 16; i += 256) {
        int r = i >> 4, k4 = i & 15;
        int row = row0 + r;
        float4 v = make_float4(0.f, 0.f, 0.f, 0.f);
        if (row < N_NODES)
            v = reinterpret_cast<const float4*>(src)[(size_t)row * 16 + k4];
        *reinterpret_cast<float4*>(&As[r * SROW + k4 * 4]) = v;
    }
}

__device__ __forceinline__ void gemm_tile(const float* As, const float* Ws,
                                          unsigned long long acc[4][4],
                                          int tx, int ty) {
    #pragma unroll 4
    for (int k4 = 0; k4 < 16; k4++) {
        ulonglong2 a[4], w[4];
        #pragma unroll
        for (int ri = 0; ri < 4; ri++)
            a[ri] = *reinterpret_cast<const ulonglong2*>(&As[(ty * 4 + ri) * SROW + k4 * 4]);
        #pragma unroll
        for (int ji = 0; ji < 4; ji++)
            w[ji] = *reinterpret_cast<const ulonglong2*>(&Ws[(tx + 16 * ji) * SROW + k4 * 4]);
        #pragma unroll
        for (int ri = 0; ri < 4; ri++)
            #pragma unroll
            for (int ji = 0; ji < 4; ji++) {
                asm("fma.rn.f32x2 %0, %1, %2, %0;"
                    : "+l"(acc[ri][ji]) : "l"(a[ri].x), "l"(w[ji].x));
                asm("fma.rn.f32x2 %0, %1, %2, %0;"
                    : "+l"(acc[ri][ji]) : "l"(a[ri].y), "l"(w[ji].y));
            }
    }
}

__global__ __launch_bounds__(256) void dual_linear_kernel(
        float* __restrict__ hid, float* __restrict__ out,
        const float* __restrict__ W, const float* __restrict__ b) {
    __shared__ __align__(16) float As[64 * SROW];
    __shared__ __align__(16) float Ws[64 * SROW];

    const int t = threadIdx.x;           // 256 threads
    const int row0 = blockIdx.x * 64;
    const int tx = t & 15;
    const int ty = t >> 4;

    // ---- phase 1: hid = A1 @ W^T + b ----
    #pragma unroll
    for (int i = t; i < 64 * 16; i += 256) {
        int j = i >> 4, k4 = i & 15;
        *reinterpret_cast<float4*>(&Ws[j * SROW + k4 * 4]) =
            reinterpret_cast<const float4*>(W)[j * 16 + k4];
    }
    stage_a_tile(As, g_a1, row0, t);
    __syncthreads();

    {
        unsigned long long acc[4][4];
        #pragma unroll
        for (int ri = 0; ri < 4; ri++)
            #pragma unroll
            for (int ji = 0; ji < 4; ji++) acc[ri][ji] = 0ull;
        gemm_tile(As, Ws, acc, tx, ty);
        float bj[4];
        #pragma unroll
        for (int ji = 0; ji < 4; ji++) bj[ji] = __ldg(&b[tx + 16 * ji]);
        #pragma unroll
        for (int ri = 0; ri < 4; ri++) {
            int row = row0 + ty * 4 + ri;
            if (row < N_NODES) {
                #pragma unroll
                for (int ji = 0; ji < 4; ji++) {
                    float lo, hi;
                    asm("mov.b64 {%0, %1}, %2;" : "=f"(lo), "=f"(hi) : "l"(acc[ri][ji]));
                    hid[(size_t)row * D + tx + 16 * ji] = lo + hi + bj[ji];
                }
            }
        }
    }
    __syncthreads();

    // ---- phase 2: out = A2 @ W2^T + deg*bW + b ----
    #pragma unroll
    for (int i = t; i < 64 * 16; i += 256) {
        int j = i >> 4, k4 = i & 15;
        *reinterpret_cast<float4*>(&Ws[j * SROW + k4 * 4]) =
            reinterpret_cast<const float4*>(g_W2)[j * 16 + k4];
    }
    stage_a_tile(As, g_a2, row0, t);
    __syncthreads();

    {
        unsigned long long acc[4][4];
        #pragma unroll
        for (int ri = 0; ri < 4; ri++)
            #pragma unroll
            for (int ji = 0; ji < 4; ji++) acc[ri][ji] = 0ull;
        gemm_tile(As, Ws, acc, tx, ty);
        float bj[4], bWj[4];
        #pragma unroll
        for (int ji = 0; ji < 4; ji++) {
            bj[ji]  = __ldg(&b[tx + 16 * ji]);
            bWj[ji] = __ldg(&g_bW[tx + 16 * ji]);
        }
        #pragma unroll
        for (int ri = 0; ri < 4; ri++) {
            int row = row0 + ty * 4 + ri;
            if (row < N_NODES) {
                float degf = __int2float_rn(__ldg(&g_deg[row]));
                #pragma unroll
                for (int ji = 0; ji < 4; ji++) {
                    float lo, hi;
                    asm("mov.b64 {%0, %1}, %2;" : "=f"(lo), "=f"(hi) : "l"(acc[ri][ji]));
                    out[(size_t)row * D + tx + 16 * ji] = lo + hi + degf * bWj[ji] + bj[ji];
                }
            }
        }
    }
}

// ---------------------------------------------------------------------------
extern "C" void kernel_launch(void* const* d_in, const int* in_sizes, int n_in,
                              void* d_out, int out_size) {
    const float* x  = (const float*)d_in[0];
    const void*  ei = d_in[1];
    const float* W1 = (const float*)d_in[2];
    const float* b1 = (const float*)d_in[3];

    float* out = (float*)d_out;                      // (out, hid) flattened
    float* hid = out + (size_t)N_NODES * D;

    const int E4BLK = (N_EDGES / 4 + 255) / 256;     // 1221
    const int GBLK  = (N_NODES * 16 + 255) / 256;    // 6250
    const int FBLK  = (N_NODES + 63) / 64;           // 1563

    init2_kernel<<<ZBLKS + 17, 256>>>((const unsigned*)ei, W1, b1);
    hist_kernel<<<E4BLK, 256>>>(ei);
    scanoff_kernel<<<ZBLKS, 256>>>();
    fill_kernel<<<E4BLK, 256>>>(ei);
    gather_kernel<<<GBLK, 256>>>(x, 0);              // A1 = agg(x)
    gather_kernel<<<GBLK, 256>>>(x, 1);              // A2 = agg(A1)
    dual_linear_kernel<<<FBLK, 256>>>(hid, out, W1, b1);
}